// round 1
// baseline (speedup 1.0000x reference)
#include <cuda_runtime.h>
#include <math.h>

#define NB   4
#define CHN  256
#define NHW  4096
#define MALL 320   // 32 (b) + 32 (c) + 256 (d)

// Scratch (device globals -- allocation is forbidden)
__device__ float g_bcd[(size_t)NB * NHW * MALL];   // [n][i][320]  ~21 MB
__device__ float g_S[(size_t)NB * NHW * NHW];      // raw scores   ~268 MB
__device__ float g_m[NB * NHW];                    // row max
__device__ float g_l[NB * NHW];                    // row sum of exp(s-m)

typedef unsigned long long ull;

__device__ __forceinline__ ull pack2(float lo, float hi) {
    ull r; asm("mov.b64 %0, {%1, %2};" : "=l"(r) : "f"(lo), "f"(hi)); return r;
}
__device__ __forceinline__ ull fma2(ull a, ull b, ull c) {
    ull d; asm("fma.rn.f32x2 %0, %1, %2, %3;" : "=l"(d) : "l"(a), "l"(b), "l"(c)); return d;
}
__device__ __forceinline__ float2 unpack2(ull v) {
    float2 f; asm("mov.b64 {%0, %1}, %2;" : "=f"(f.x), "=f"(f.y) : "l"(v)); return f;
}

// ---------------------------------------------------------------------------
// K1: fused 1x1 convs.  g_bcd[n][i][m] = sum_ch W[m][ch]*a[n][ch][i] + bias[m]
// Block: 256 threads, each owns one pixel i; one m-tile of 32 per block.
// Grid: (16 i-blocks, 10 m-tiles, 4 batches)
// ---------------------------------------------------------------------------
__global__ __launch_bounds__(256) void k1_conv(
    const float* __restrict__ a,
    const float* __restrict__ b_w, const float* __restrict__ b_b,
    const float* __restrict__ c_w, const float* __restrict__ c_b,
    const float* __restrict__ d_w, const float* __restrict__ d_b)
{
    __shared__ float w_s[256][36];   // [ch][mm], pad 36 -> 144B rows (16B aligned)
    const int t  = threadIdx.x;
    const int n  = blockIdx.z;
    const int m0 = blockIdx.y * 32;
    const int i  = blockIdx.x * 256 + t;

    // cooperative W tile load (coalesced along ch), transposed store
    for (int k = 0; k < 32; k++) {
        int idx = t + k * 256;           // 8192 total
        int ch = idx & 255, mm = idx >> 8;
        int m = m0 + mm;
        const float* wr = (m < 32) ? (b_w + m * 256)
                        : (m < 64) ? (c_w + (m - 32) * 256)
                                   : (d_w + (m - 64) * 256);
        w_s[ch][mm] = wr[ch];
    }
    __syncthreads();

    ull acc[16];
#pragma unroll
    for (int q = 0; q < 16; q++) {
        int m = m0 + 2 * q;
        float bl = (m < 32) ? b_b[m] : (m < 64) ? c_b[m - 32] : d_b[m - 64];
        int m1 = m + 1;
        float bh = (m1 < 32) ? b_b[m1] : (m1 < 64) ? c_b[m1 - 32] : d_b[m1 - 64];
        acc[q] = pack2(bl, bh);
    }

    const float* ap = a + (size_t)n * CHN * NHW + i;
#pragma unroll 4
    for (int ch = 0; ch < 256; ch++) {
        float av = __ldg(ap + (size_t)ch * NHW);
        ull a2 = pack2(av, av);
        const float4* wrow = (const float4*)&w_s[ch][0];
#pragma unroll
        for (int q = 0; q < 8; q++) {
            float4 wv = wrow[q];
            acc[2 * q]     = fma2(a2, pack2(wv.x, wv.y), acc[2 * q]);
            acc[2 * q + 1] = fma2(a2, pack2(wv.z, wv.w), acc[2 * q + 1]);
        }
    }

    float* outp = g_bcd + ((size_t)n * NHW + i) * MALL + m0;
#pragma unroll
    for (int q = 0; q < 8; q++) {
        float2 x = unpack2(acc[2 * q]);
        float2 y = unpack2(acc[2 * q + 1]);
        ((float4*)outp)[q] = make_float4(x.x, x.y, y.x, y.y);
    }
}

// ---------------------------------------------------------------------------
// K2: scores S[i][j] = b_i . c_j  (K=32), stored raw to g_S, plus online
// softmax stats (m,l) per row.  Block = 16 query rows x 256 threads
// (16 threads per row, each covering j strided).  Grid: (256, 4)
// ---------------------------------------------------------------------------
__global__ __launch_bounds__(256) void k2_scores()
{
    __shared__ float c_s[64][36];    // j-tile of 64 c-rows, pad 36
    const int t  = threadIdx.x;
    const int n  = blockIdx.y;
    const int i0 = blockIdx.x * 16;
    const int r  = t >> 4;           // row 0..15
    const int jj = t & 15;

    // q row (32 floats) packed into 16 f32x2 pairs, kept in registers
    ull q2[16];
    {
        const float4* qp = (const float4*)(g_bcd + ((size_t)n * NHW + i0 + r) * MALL);
#pragma unroll
        for (int k = 0; k < 8; k++) {
            float4 v = qp[k];
            q2[2 * k]     = pack2(v.x, v.y);
            q2[2 * k + 1] = pack2(v.z, v.w);
        }
    }

    float m = -INFINITY, l = 0.0f;
    float* srow = g_S + ((size_t)(n * NHW + i0 + r)) * NHW;

    for (int jt = 0; jt < NHW; jt += 64) {
        __syncthreads();
        // cooperative load of 64 c-rows (c = bcd[32:64]), coalesced
#pragma unroll
        for (int k = 0; k < 8; k++) {
            int idx = t + k * 256;               // 2048
            int row = idx >> 5, col = idx & 31;
            c_s[row][col] = g_bcd[((size_t)n * NHW + jt + row) * MALL + 32 + col];
        }
        __syncthreads();

#pragma unroll
        for (int h = 0; h < 4; h++) {
            int jl = jj + h * 16;
            const float4* cp = (const float4*)&c_s[jl][0];
            ull s2a = 0ULL, s2b = 0ULL;
#pragma unroll
            for (int k = 0; k < 4; k++) {
                float4 v0 = cp[2 * k];
                float4 v1 = cp[2 * k + 1];
                s2a = fma2(pack2(v0.x, v0.y), q2[4 * k],     s2a);
                s2b = fma2(pack2(v0.z, v0.w), q2[4 * k + 1], s2b);
                s2a = fma2(pack2(v1.x, v1.y), q2[4 * k + 2], s2a);
                s2b = fma2(pack2(v1.z, v1.w), q2[4 * k + 3], s2b);
            }
            float2 xa = unpack2(s2a), xb = unpack2(s2b);
            float s = (xa.x + xa.y) + (xb.x + xb.y);
            srow[jt + jl] = s;
            // online softmax stats (1 exp in the common path)
            if (s > m) { l = l * __expf(m - s) + 1.0f; m = s; }
            else       { l += __expf(s - m); }
        }
    }

    // reduce (m,l) across the 16 lanes that share this row
#pragma unroll
    for (int off = 8; off >= 1; off >>= 1) {
        float m2 = __shfl_xor_sync(0xffffffffu, m, off);
        float l2 = __shfl_xor_sync(0xffffffffu, l, off);
        float mn = fmaxf(m, m2);
        l = l * __expf(m - mn) + l2 * __expf(m2 - mn);
        m = mn;
    }
    if (jj == 0) {
        g_m[n * NHW + i0 + r] = m;
        g_l[n * NHW + i0 + r] = l;
    }
}

// ---------------------------------------------------------------------------
// K3: out[n][c][i] = (alpha / l_i) * sum_j exp(S[i][j]-m_i) * d[c][j] + a[n][c][i]
// GEMM M=4096(i) x N=256(c) x K=4096(j) per batch, exp fused into smem staging.
// Block tile 128i x 128c, 8x8 micro-tile, f32x2 inner loop.
// Grid: (2 c-tiles, 32 i-tiles, 4 batches)
// ---------------------------------------------------------------------------
__global__ __launch_bounds__(256, 2) void k3_pv(
    const float* __restrict__ a,
    const float* __restrict__ alphap,
    float* __restrict__ out)
{
    __shared__ float p_s[16][132];   // [j][i], pad 132 -> 528B rows (16B aligned)
    __shared__ float d_s[16][128];   // [j][c]
    __shared__ float m_s[128], l_s[128];

    const int t  = threadIdx.x;
    const int n  = blockIdx.z;
    const int i0 = blockIdx.y * 128;
    const int c0 = blockIdx.x * 128;
    const int ti = t & 15;           // i micro-group
    const int tc = t >> 4;           // c micro-group

    if (t < 128) {
        m_s[t] = g_m[n * NHW + i0 + t];
        l_s[t] = g_l[n * NHW + i0 + t];
    }
    ull acc[32];
#pragma unroll
    for (int q = 0; q < 32; q++) acc[q] = 0ULL;
    __syncthreads();

    for (int jt = 0; jt < NHW; jt += 16) {
        // d tile: 16 j-rows x 128 c, coalesced
#pragma unroll
        for (int k = 0; k < 8; k++) {
            int idx = t + k * 256;
            int row = idx >> 7, col = idx & 127;
            d_s[row][col] = g_bcd[((size_t)n * NHW + jt + row) * MALL + 64 + c0 + col];
        }
        // p tile: exp(S - m) applied while staging, stored transposed [j][i]
#pragma unroll
        for (int k = 0; k < 8; k++) {
            int idx = t + k * 256;
            int ii = idx >> 4, jl = idx & 15;
            float s = g_S[((size_t)(n * NHW + i0 + ii)) * NHW + jt + jl];
            p_s[jl][ii] = __expf(s - m_s[ii]);
        }
        __syncthreads();

#pragma unroll
        for (int j = 0; j < 16; j++) {
            float4 pa = *(const float4*)&p_s[j][ti * 8];
            float4 pb = *(const float4*)&p_s[j][ti * 8 + 4];
            float4 da = *(const float4*)&d_s[j][tc * 8];
            float4 db = *(const float4*)&d_s[j][tc * 8 + 4];
            ull pp[8] = { pack2(pa.x, pa.x), pack2(pa.y, pa.y),
                          pack2(pa.z, pa.z), pack2(pa.w, pa.w),
                          pack2(pb.x, pb.x), pack2(pb.y, pb.y),
                          pack2(pb.z, pb.z), pack2(pb.w, pb.w) };
            ull dd[4] = { pack2(da.x, da.y), pack2(da.z, da.w),
                          pack2(db.x, db.y), pack2(db.z, db.w) };
#pragma unroll
            for (int iq = 0; iq < 8; iq++)
#pragma unroll
                for (int cq = 0; cq < 4; cq++)
                    acc[iq * 4 + cq] = fma2(pp[iq], dd[cq], acc[iq * 4 + cq]);
        }
        __syncthreads();
    }

    const float alpha = alphap[0];
    float inv[8];
#pragma unroll
    for (int iq = 0; iq < 8; iq++) inv[iq] = alpha / l_s[ti * 8 + iq];

#pragma unroll
    for (int cq = 0; cq < 8; cq++) {
        int c = c0 + tc * 8 + cq;
        const float* ap = a   + ((size_t)n * CHN + c) * NHW + i0 + ti * 8;
        float*       op = out + ((size_t)n * CHN + c) * NHW + i0 + ti * 8;
        float o[8];
#pragma unroll
        for (int iq = 0; iq < 8; iq++) {
            float2 x = unpack2(acc[iq * 4 + (cq >> 1)]);
            o[iq] = (cq & 1) ? x.y : x.x;
        }
        float4 a0 = ((const float4*)ap)[0];
        float4 a1 = ((const float4*)ap)[1];
        ((float4*)op)[0] = make_float4(o[0] * inv[0] + a0.x, o[1] * inv[1] + a0.y,
                                       o[2] * inv[2] + a0.z, o[3] * inv[3] + a0.w);
        ((float4*)op)[1] = make_float4(o[4] * inv[4] + a1.x, o[5] * inv[5] + a1.y,
                                       o[6] * inv[6] + a1.z, o[7] * inv[7] + a1.w);
    }
}

// ---------------------------------------------------------------------------
extern "C" void kernel_launch(void* const* d_in, const int* in_sizes, int n_in,
                              void* d_out, int out_size)
{
    const float* a     = (const float*)d_in[0];
    const float* b_w   = (const float*)d_in[1];
    const float* b_b   = (const float*)d_in[2];
    const float* c_w   = (const float*)d_in[3];
    const float* c_b   = (const float*)d_in[4];
    const float* d_w   = (const float*)d_in[5];
    const float* d_b   = (const float*)d_in[6];
    const float* alpha = (const float*)d_in[7];
    float* out = (float*)d_out;

    k1_conv<<<dim3(16, 10, 4), 256>>>(a, b_w, b_b, c_w, c_b, d_w, d_b);
    k2_scores<<<dim3(256, 4), 256>>>();
    k3_pv<<<dim3(2, 32, 4), 256>>>(a, alpha, out);
}